// round 15
// baseline (speedup 1.0000x reference)
#include <cuda_runtime.h>
#include <cuda_bf16.h>

#define B_    512
#define BAG_  32
#define H_    1024
#define C_    53
#define N_    (B_*BAG_)   // 16384
#define EPS_  1e-8f
#define NSLOT 16

// ---------------- device scratch ----------------
__device__ __align__(128) __nv_bfloat16 g_rep_bf[N_*H_];
__device__ __align__(128) __nv_bfloat16 g_bag_bf[B_*H_];
__device__ float g_bag[B_*H_];
__device__ float g_rnb[B_];
__device__ float g_rnr[N_];
__device__ float g_pos[N_];
__device__ float g_negp[NSLOT][N_];
__device__ float g_lsum;
__device__ int   g_tick = 0;   // k_pair CTA completion tickets
__device__ int   g_pcnt = 0;   // k_pos block completions
__device__ int   g_cnt2 = 0;   // loss finalize counter

__device__ __forceinline__ float warp_sum(float v) {
    #pragma unroll
    for (int o = 16; o; o >>= 1) v += __shfl_down_sync(0xffffffffu, v, o);
    return v;
}
__device__ __forceinline__ float warp_max(float v) {
    #pragma unroll
    for (int o = 16; o; o >>= 1) v = fmaxf(v, __shfl_xor_sync(0xffffffffu, v, o));
    return v;
}

// fast exp on the FMA pipe: no MUFU, no CVT. |x| <= 20, rel err < 3e-6.
__device__ __forceinline__ float fexp(float x) {
    const float LOG2E = 1.4426950408889634f;
    float z = fmaf(x, LOG2E, 12582912.0f);
    int   iz = __float_as_int(z);
    float r  = z - 12582912.0f;
    float f  = fmaf(x, LOG2E, -r);
    float p =            1.3298820e-3f;
    p = fmaf(p, f, 9.6179670e-3f);
    p = fmaf(p, f, 5.5503645e-2f);
    p = fmaf(p, f, 2.4022645e-1f);
    p = fmaf(p, f, 6.9314718e-1f);
    p = fmaf(p, f, 1.0f);
    unsigned sc = ((unsigned)iz + (127u - 0x4B400000u)) << 23;
    return p * __int_as_float(sc);
}

// ---------------- PTX helpers ----------
#define MBAR_INIT(addr, cnt) \
    asm volatile("mbarrier.init.shared.b64 [%0], %1;" :: "r"(addr), "r"(cnt) : "memory")

#define MBAR_WAIT(addr, par) do {                                              \
    unsigned _m = (addr), _p = (par), _d;                                      \
    asm volatile("{\n\t.reg .pred p;\n\t"                                      \
        "mbarrier.try_wait.parity.acquire.cta.shared::cta.b64 p, [%1], %2;\n\t"\
        "selp.b32 %0,1,0,p;\n\t}" : "=r"(_d) : "r"(_m), "r"(_p) : "memory");   \
    if (!_d) {                                                                 \
        asm volatile("{\n\t.reg .pred P1;\n\t"                                 \
        "WL_%=:\n\t"                                                           \
        "mbarrier.try_wait.parity.acquire.cta.shared::cta.b64 P1, [%0], %1, 0x989680;\n\t" \
        "@P1 bra.uni WD_%=;\n\t"                                               \
        "bra.uni WL_%=;\n\t"                                                   \
        "WD_%=:\n\t}" :: "r"(_m), "r"(_p) : "memory");                         \
    }                                                                          \
} while (0)

#define MBAR_ARRIVE(addr) \
    asm volatile("mbarrier.arrive.shared.b64 _, [%0];" :: "r"(addr) : "memory")

#define LDSM4(r, addr) \
    asm volatile("ldmatrix.sync.aligned.m8n8.x4.shared.b16 {%0,%1,%2,%3}, [%4];" \
        : "=r"((r)[0]), "=r"((r)[1]), "=r"((r)[2]), "=r"((r)[3]) : "r"(addr))

#define MMA_BF16(c, a, b0v, b1v) \
    asm volatile("mma.sync.aligned.m16n8k16.row.col.f32.bf16.bf16.f32 " \
        "{%0,%1,%2,%3}, {%4,%5,%6,%7}, {%8,%9}, {%0,%1,%2,%3};" \
        : "+f"((c)[0]), "+f"((c)[1]), "+f"((c)[2]), "+f"((c)[3]) \
        : "r"((a)[0]), "r"((a)[1]), "r"((a)[2]), "r"((a)[3]), "r"(b0v), "r"(b1v))

__device__ __forceinline__ void bulk_cp(unsigned dst, const void* src,
                                        unsigned bytes, unsigned mbar) {
    asm volatile(
        "cp.async.bulk.shared::cta.global.mbarrier::complete_tx::bytes [%0], [%1], %2, [%3];"
        :: "r"(dst), "l"(src), "r"(bytes), "r"(mbar) : "memory");
}
__device__ __forceinline__ void mbar_expect(unsigned mbar, unsigned bytes) {
    asm volatile("mbarrier.arrive.expect_tx.shared.b64 _, [%0], %1;"
                 :: "r"(mbar), "r"(bytes) : "memory");
}
__device__ __forceinline__ unsigned sw128(unsigned byo) {
    return byo ^ ((byo >> 3) & 0x70);
}
__device__ __forceinline__ unsigned bf2u(__nv_bfloat162 h) {
    return *(unsigned*)&h;
}

// ---------------- K1: rep-only bag pooling (exact R8) -----------------------
__global__ void __launch_bounds__(256) k_bag(
    const float* __restrict__ rep,
    const float* __restrict__ rel_table, const int* __restrict__ labels)
{
    __shared__ float s_scores[BAG_];
    __shared__ float s_alpha[BAG_];
    __shared__ float s_red[8];

    int b = blockIdx.x;
    int tid = threadIdx.x, wid = tid >> 5, lane = tid & 31;
    const float* repb = rep + (size_t)b * BAG_ * H_;
    const float4* rel4 = (const float4*)(rel_table + (size_t)labels[b] * H_);

    #pragma unroll
    for (int q = 0; q < 2; ++q)
        g_negp[wid + q * 8][b * BAG_ + lane] = 0.0f;
    if (b == 0 && tid == 0) {
        g_lsum = 0.0f; g_tick = 0; g_pcnt = 0; g_cnt2 = 0;
    }

    for (int j = wid; j < BAG_; j += 8) {
        const float4* r4 = (const float4*)(repb + (size_t)j * H_);
        int n = b * BAG_ + j;
        char* dstb = (char*)g_rep_bf + (size_t)(n >> 3) * 1024;
        unsigned inoff = sw128((unsigned)(n & 7) * 128u + (unsigned)(lane & 15) * 8u);
        float ds = 0.f, dr = 0.f;
        #pragma unroll
        for (int i = 0; i < 8; ++i) {
            int t = lane + 32 * i;
            float4 rv = r4[t];
            float4 rl = rel4[t];
            uint2 pk;
            pk.x = bf2u(__floats2bfloat162_rn(rv.x, rv.y));
            pk.y = bf2u(__floats2bfloat162_rn(rv.z, rv.w));
            unsigned kc = (unsigned)(lane >> 4) + 2u * i;
            *(uint2*)(dstb + (size_t)kc * (N_ * 128) + inoff) = pk;
            ds = fmaf(rl.x, rv.x, fmaf(rl.y, rv.y, fmaf(rl.z, rv.z, fmaf(rl.w, rv.w, ds))));
            dr = fmaf(rv.x, rv.x, fmaf(rv.y, rv.y, fmaf(rv.z, rv.z, fmaf(rv.w, rv.w, dr))));
        }
        ds = warp_sum(ds); dr = warp_sum(dr);
        if (lane == 0) {
            s_scores[j] = ds * (1.0f / 32.0f);          // / sqrt(H)
            g_rnr[n] = 1.0f / sqrtf(dr);
        }
    }
    __syncthreads();

    if (tid < 32) {
        float v = s_scores[tid];
        float m = warp_max(v);
        float e = expf(v - m);
        float s = warp_sum(e);
        s = __shfl_sync(0xffffffffu, s, 0);
        s_alpha[tid] = e / s;
    }
    __syncthreads();

    const float4* rp4 = (const float4*)repb;
    float4 acc = make_float4(0.f, 0.f, 0.f, 0.f);
    #pragma unroll 8
    for (int j = 0; j < BAG_; ++j) {
        float4 v = rp4[(size_t)j * 256 + tid];
        float a = s_alpha[j];
        acc.x = fmaf(a, v.x, acc.x); acc.y = fmaf(a, v.y, acc.y);
        acc.z = fmaf(a, v.z, acc.z); acc.w = fmaf(a, v.w, acc.w);
    }
    ((float4*)g_bag)[(size_t)b * 256 + tid] = acc;
    {
        uint2 pk;
        pk.x = bf2u(__floats2bfloat162_rn(acc.x, acc.y));
        pk.y = bf2u(__floats2bfloat162_rn(acc.z, acc.w));
        unsigned kc = (unsigned)tid >> 4;
        unsigned sw = sw128((unsigned)(b & 7) * 128u + (unsigned)(tid & 15) * 8u);
        *(uint2*)((char*)g_bag_bf + (size_t)kc * (B_ * 128) + (size_t)(b >> 3) * 1024 + sw) = pk;
    }
    float nb_part = fmaf(acc.x, acc.x, fmaf(acc.y, acc.y, fmaf(acc.z, acc.z, acc.w * acc.w)));
    nb_part = warp_sum(nb_part);
    if (lane == 0) s_red[wid] = nb_part;
    __syncthreads();
    if (tid == 0) {
        float s = 0.f;
        #pragma unroll
        for (int w = 0; w < 8; ++w) s += s_red[w];
        g_rnb[b] = 1.0f / sqrtf(s);
    }
}

// ---------------- K1b: pos term + completion counter ------------------------
__global__ void __launch_bounds__(256) k_pos(
    const float* __restrict__ rep, const float* __restrict__ aug,
    const float* __restrict__ tptr)
{
    int b = blockIdx.x;
    int tid = threadIdx.x, wid = tid >> 5, lane = tid & 31;
    float invT = 1.0f / tptr[0];

    for (int j = wid; j < BAG_; j += 8) {
        int n = b * BAG_ + j;
        const float4* r4 = (const float4*)(rep + (size_t)n * H_);
        const float4* a4 = (const float4*)(aug + (size_t)n * H_);
        float da = 0.f, dra = 0.f;
        #pragma unroll
        for (int i = 0; i < 8; ++i) {
            int t = lane + 32 * i;
            float4 rv = r4[t], av = a4[t];
            da  = fmaf(av.x, av.x, fmaf(av.y, av.y, fmaf(av.z, av.z, fmaf(av.w, av.w, da))));
            dra = fmaf(rv.x, av.x, fmaf(rv.y, av.y, fmaf(rv.z, av.z, fmaf(rv.w, av.w, dra))));
        }
        da = warp_sum(da); dra = warp_sum(dra);
        if (lane == 0) {
            float na = sqrtf(da);
            float nr = 1.0f / g_rnr[n];
            float psim = dra / fmaxf(nr * na, EPS_);
            g_pos[n] = expf(psim * invT);
        }
    }
    __syncthreads();
    if (tid == 0) {
        __threadfence();               // release g_pos writes
        atomicAdd(&g_pcnt, 1);
    }
}

// ---------------- K2: classifier, 64 blocks x 8 bag rows -------------------
__global__ void __launch_bounds__(256) k_clsout(
    const float* __restrict__ cls_w, const float* __restrict__ cls_b,
    float* __restrict__ out)
{
    __shared__ float4 sbag[8][256];
    int tid = threadIdx.x, wid = tid >> 5, lane = tid & 31;
    int b0 = blockIdx.x * 8;
    for (int idx = tid; idx < 2048; idx += 256)
        sbag[idx >> 8][idx & 255] =
            ((const float4*)g_bag)[(size_t)(b0 + (idx >> 8)) * 256 + (idx & 255)];
    __syncthreads();

    for (int c0 = wid * 2; c0 < C_; c0 += 16) {
        int c1 = c0 + 1;
        bool has1 = c1 < C_;
        const float4* w0 = (const float4*)(cls_w + (size_t)c0 * H_);
        const float4* w1 = (const float4*)(cls_w + (size_t)(has1 ? c1 : c0) * H_);
        float acc0[8] = {}, acc1[8] = {};
        for (int i = lane; i < 256; i += 32) {
            float4 wa = w0[i], wb = w1[i];
            #pragma unroll
            for (int r = 0; r < 8; ++r) {
                float4 v = sbag[r][i];
                acc0[r] = fmaf(wa.x, v.x, fmaf(wa.y, v.y, fmaf(wa.z, v.z, fmaf(wa.w, v.w, acc0[r]))));
                acc1[r] = fmaf(wb.x, v.x, fmaf(wb.y, v.y, fmaf(wb.z, v.z, fmaf(wb.w, v.w, acc1[r]))));
            }
        }
        #pragma unroll
        for (int r = 0; r < 8; ++r) {
            float s0 = warp_sum(acc0[r]);
            float s1 = warp_sum(acc1[r]);
            if (lane == 0) {
                out[(b0 + r) * C_ + c0] = s0 + cls_b[c0];
                if (has1) out[(b0 + r) * C_ + c1] = s1 + cls_b[c1];
            }
        }
    }
}

// ---------------- K3: bf16 HMMA pair GEMM (R8-exact) + fused loss tail -----
#define STAGES 3
#define STAGE_BYTES 32768
#define NKC 16
#define PAIR_SMEM (STAGES * STAGE_BYTES)   // 98304

__global__ void __launch_bounds__(256, 2) k_pair_hmma(const float* __restrict__ tptr,
                                                      float* __restrict__ out,
                                                      int loss_idx)
{
    extern __shared__ __align__(16) char smem[];
    __shared__ __align__(8) unsigned long long mbars[2 * STAGES];
    __shared__ int s_tick;
    __shared__ float sr[8];
    unsigned smem_u = (unsigned)__cvta_generic_to_shared(smem);
    unsigned mbar_u = (unsigned)__cvta_generic_to_shared(mbars);
    int tid = threadIdx.x, wid = tid >> 5, lane = tid & 31;
    int wm = wid >> 2, wn = wid & 3;
    int m0 = blockIdx.y * 128, n0 = blockIdx.x * 128;

    if (tid == 0) {
        #pragma unroll
        for (int s = 0; s < STAGES; ++s) {
            MBAR_INIT(mbar_u + 8 * s, 1);
            MBAR_INIT(mbar_u + 8 * (STAGES + s), 8);
        }
    }
    __syncthreads();

    const char* Asrc = (const char*)g_bag_bf;
    const char* Bsrc = (const char*)g_rep_bf;
    if (tid == 0) {
        #pragma unroll
        for (int s = 0; s < STAGES; ++s) {
            unsigned mb = mbar_u + 8 * s;
            mbar_expect(mb, 2 * 16384u);
            unsigned d = smem_u + s * STAGE_BYTES;
            bulk_cp(d,          Asrc + ((size_t)s * B_ + m0) * 128, 16384u, mb);
            bulk_cp(d + 16384u, Bsrc + ((size_t)s * N_ + n0) * 128, 16384u, mb);
        }
    }

    unsigned xr   = (unsigned)(lane & 7) * 16u;
    unsigned hk16 = (unsigned)(lane >> 4) * 16u;
    unsigned kb16 = (unsigned)((lane >> 3) & 1) * 16u;
    unsigned aoffb = (unsigned)((wm * 64 + (lane & 15)) * 128);
    unsigned boffb = (unsigned)((wn * 32 + ((lane >> 4) & 1) * 8 + (lane & 7)) * 128) + 16384u;

    float acc[4][4][4] = {};

    #pragma unroll 1
    for (int kc = 0; kc < NKC; ++kc) {
        int st = kc % 3;
        unsigned u = (unsigned)(kc / 3);
        MBAR_WAIT(mbar_u + 8 * st, u & 1);
        unsigned base = smem_u + st * STAGE_BYTES;
        #pragma unroll
        for (int ks = 0; ks < 4; ++ks) {
            unsigned afr[4][4], bfr[2][4];
            unsigned ksa = ((unsigned)(ks * 32) + hk16) ^ xr;
            unsigned ksb = ((unsigned)(ks * 32) + kb16) ^ xr;
            #pragma unroll
            for (int mt = 0; mt < 4; ++mt)
                LDSM4(afr[mt], base + aoffb + mt * 2048u + ksa);
            #pragma unroll
            for (int np = 0; np < 2; ++np)
                LDSM4(bfr[np], base + boffb + np * 2048u + ksb);
            #pragma unroll
            for (int mt = 0; mt < 4; ++mt)
                #pragma unroll
                for (int nt = 0; nt < 4; ++nt)
                    MMA_BF16(acc[mt][nt], afr[mt],
                             bfr[nt >> 1][(nt & 1) * 2], bfr[nt >> 1][(nt & 1) * 2 + 1]);
        }
        if (lane == 0) MBAR_ARRIVE(mbar_u + 8 * (STAGES + st));
        if (kc + STAGES < NKC && wid == (kc & 7) && lane == 0) {
            MBAR_WAIT(mbar_u + 8 * (STAGES + st), u & 1);
            unsigned mb = mbar_u + 8 * st;
            mbar_expect(mb, 2 * 16384u);
            unsigned d = smem_u + st * STAGE_BYTES;
            bulk_cp(d,          Asrc + ((size_t)(kc + STAGES) * B_ + m0) * 128, 16384u, mb);
            bulk_cp(d + 16384u, Bsrc + ((size_t)(kc + STAGES) * N_ + n0) * 128, 16384u, mb);
        }
    }
    __syncthreads();

    // ---- epilogue: FMA-pipe exp, single-pass smem reduce, slotted atomics ----
    float* sbuf  = (float*)smem;                    // [4][128][33]
    float* s_rnr = (float*)(smem + 67584);
    float* s_rnb = (float*)(smem + 67584 + 512);
    if (tid < 128) { s_rnr[tid] = g_rnr[n0 + tid]; s_rnb[tid] = g_rnb[m0 + tid]; }
    __syncthreads();
    float invT = 1.0f / tptr[0];
    int bglob = (n0 >> 5) + wn;
    int r0base = wm * 64 + (lane >> 2);
    float* negslot = g_negp[blockIdx.x & (NSLOT - 1)];
    float* wbuf = sbuf + wn * (128 * 33);

    #pragma unroll
    for (int mt = 0; mt < 4; ++mt) {
        int r0 = r0base + mt * 16, r1 = r0 + 8;
        float f0 = s_rnb[r0] * invT, f1 = s_rnb[r1] * invT;
        bool sk0 = (m0 + r0) == bglob, sk1 = (m0 + r1) == bglob;
        #pragma unroll
        for (int nt = 0; nt < 4; ++nt) {
            int jj = nt * 8 + (lane & 3) * 2;
            float rn0 = s_rnr[wn * 32 + jj], rn1 = s_rnr[wn * 32 + jj + 1];
            float e00 = sk0 ? 0.f : fexp(acc[mt][nt][0] * f0 * rn0);
            float e01 = sk0 ? 0.f : fexp(acc[mt][nt][1] * f0 * rn1);
            float e10 = sk1 ? 0.f : fexp(acc[mt][nt][2] * f1 * rn0);
            float e11 = sk1 ? 0.f : fexp(acc[mt][nt][3] * f1 * rn1);
            wbuf[r0 * 33 + jj]     = e00;
            wbuf[r0 * 33 + jj + 1] = e01;
            wbuf[r1 * 33 + jj]     = e10;
            wbuf[r1 * 33 + jj + 1] = e11;
        }
    }
    __syncthreads();
    for (int e = tid; e < 4096; e += 256) {
        int lc = e >> 5, jj = e & 31;
        float v = sbuf[lc * 33 + jj]
                + sbuf[1 * (128 * 33) + lc * 33 + jj]
                + sbuf[2 * (128 * 33) + lc * 33 + jj]
                + sbuf[3 * (128 * 33) + lc * 33 + jj];
        atomicAdd(&negslot[(m0 + lc) * BAG_ + jj], v);
    }

    // ---- fused loss tail: last 64 CTAs (by ticket) compute the loss ---------
    __threadfence();                       // release this CTA's neg atomics
    __syncthreads();                       // all epilogue atomics issued
    if (tid == 0) s_tick = atomicAdd(&g_tick, 1);
    __syncthreads();
    int ticket = s_tick;
    if (ticket >= 448) {
        if (tid == 0) {
            while (*(volatile int*)&g_tick < 512) __nanosleep(128);
            while (*(volatile int*)&g_pcnt < B_)  __nanosleep(128);
        }
        __syncthreads();
        __threadfence();                   // acquire
        int i = (ticket - 448) * 256 + tid;
        float t = 0.f;
        #pragma unroll
        for (int s = 0; s < NSLOT; ++s) t += g_negp[s][i];
        float v = __logf(1.0f + __fdividef(t, g_pos[i]));
        v = warp_sum(v);
        if (lane == 0) sr[wid] = v;
        __syncthreads();
        if (tid == 0) {
            float s = 0.f;
            #pragma unroll
            for (int w = 0; w < 8; ++w) s += sr[w];
            atomicAdd(&g_lsum, s);
            __threadfence();
            if (atomicAdd(&g_cnt2, 1) == 63)
                out[loss_idx] = g_lsum * (1.0f / (float)N_);
        }
    }
}

// ---------------- launch (R8 graph minus k_loss) ----------------------------
extern "C" void kernel_launch(void* const* d_in, const int* in_sizes, int n_in,
                              void* d_out, int out_size) {
    const float* rep    = (const float*)d_in[0];
    const float* aug    = (const float*)d_in[1];
    const float* rel    = (const float*)d_in[2];
    const float* cls_w  = (const float*)d_in[3];
    const float* cls_b  = (const float*)d_in[4];
    const int*   labels = (const int*)d_in[5];
    const float* temp   = (const float*)d_in[6];
    float* out = (float*)d_out;

    static cudaStream_t s2 = nullptr;
    static cudaEvent_t evA = nullptr, evB = nullptr;
    if (!s2) {
        cudaFuncSetAttribute(k_pair_hmma, cudaFuncAttributeMaxDynamicSharedMemorySize, PAIR_SMEM);
        cudaStreamCreateWithFlags(&s2, cudaStreamNonBlocking);
        cudaEventCreateWithFlags(&evA, cudaEventDisableTiming);
        cudaEventCreateWithFlags(&evB, cudaEventDisableTiming);
    }

    // critical path: k_bag -> k_pair(+loss tail)
    k_bag<<<B_, 256>>>(rep, rel, labels);

    // fork: classifier + pos on s2, overlapping the GEMM
    cudaEventRecord(evA, 0);
    cudaStreamWaitEvent(s2, evA, 0);
    k_clsout<<<B_ / 8, 256, 0, s2>>>(cls_w, cls_b, out);
    k_pos<<<B_, 256, 0, s2>>>(rep, aug, temp);
    cudaEventRecord(evB, s2);

    dim3 g3(N_ / 128, B_ / 128);   // (128, 4)
    k_pair_hmma<<<g3, 256, PAIR_SMEM>>>(temp, out, out_size - 1);

    // join s2 on main so the graph's end covers k_clsout's writes to out
    cudaStreamWaitEvent(0, evB, 0);
}

// round 16
// speedup vs baseline: 1.1255x; 1.1255x over previous
#include <cuda_runtime.h>
#include <cuda_bf16.h>

#define B_    512
#define BAG_  32
#define H_    1024
#define C_    53
#define N_    (B_*BAG_)   // 16384
#define EPS_  1e-8f
#define NSLOT 16

// ---------------- device scratch ----------------
__device__ __align__(128) __nv_bfloat16 g_rep_bf[N_*H_];
__device__ __align__(128) __nv_bfloat16 g_bag_bf[B_*H_];
__device__ float g_bag[B_*H_];
__device__ float g_rnb[B_];
__device__ float g_rnr[N_];
__device__ float g_pos[N_];
__device__ float g_negp[NSLOT][N_];
__device__ float g_lsum;
__device__ int   g_cnt = 0;

__device__ __forceinline__ float warp_sum(float v) {
    #pragma unroll
    for (int o = 16; o; o >>= 1) v += __shfl_down_sync(0xffffffffu, v, o);
    return v;
}
__device__ __forceinline__ float warp_max(float v) {
    #pragma unroll
    for (int o = 16; o; o >>= 1) v = fmaxf(v, __shfl_xor_sync(0xffffffffu, v, o));
    return v;
}

// fast exp on the FMA pipe: no MUFU, no CVT. |x| <= 20, rel err < 3e-6.
__device__ __forceinline__ float fexp(float x) {
    const float LOG2E = 1.4426950408889634f;
    float z = fmaf(x, LOG2E, 12582912.0f);
    int   iz = __float_as_int(z);
    float r  = z - 12582912.0f;
    float f  = fmaf(x, LOG2E, -r);
    float p =            1.3298820e-3f;
    p = fmaf(p, f, 9.6179670e-3f);
    p = fmaf(p, f, 5.5503645e-2f);
    p = fmaf(p, f, 2.4022645e-1f);
    p = fmaf(p, f, 6.9314718e-1f);
    p = fmaf(p, f, 1.0f);
    unsigned sc = ((unsigned)iz + (127u - 0x4B400000u)) << 23;
    return p * __int_as_float(sc);
}

// ---------------- PTX helpers ----------
#define MBAR_INIT(addr, cnt) \
    asm volatile("mbarrier.init.shared.b64 [%0], %1;" :: "r"(addr), "r"(cnt) : "memory")

#define MBAR_WAIT(addr, par) do {                                              \
    unsigned _m = (addr), _p = (par), _d;                                      \
    asm volatile("{\n\t.reg .pred p;\n\t"                                      \
        "mbarrier.try_wait.parity.acquire.cta.shared::cta.b64 p, [%1], %2;\n\t"\
        "selp.b32 %0,1,0,p;\n\t}" : "=r"(_d) : "r"(_m), "r"(_p) : "memory");   \
    if (!_d) {                                                                 \
        asm volatile("{\n\t.reg .pred P1;\n\t"                                 \
        "WL_%=:\n\t"                                                           \
        "mbarrier.try_wait.parity.acquire.cta.shared::cta.b64 P1, [%0], %1, 0x989680;\n\t" \
        "@P1 bra.uni WD_%=;\n\t"                                               \
        "bra.uni WL_%=;\n\t"                                                   \
        "WD_%=:\n\t}" :: "r"(_m), "r"(_p) : "memory");                         \
    }                                                                          \
} while (0)

#define MBAR_ARRIVE(addr) \
    asm volatile("mbarrier.arrive.shared.b64 _, [%0];" :: "r"(addr) : "memory")

#define LDSM4(r, addr) \
    asm volatile("ldmatrix.sync.aligned.m8n8.x4.shared.b16 {%0,%1,%2,%3}, [%4];" \
        : "=r"((r)[0]), "=r"((r)[1]), "=r"((r)[2]), "=r"((r)[3]) : "r"(addr))

#define MMA_BF16(c, a, b0v, b1v) \
    asm volatile("mma.sync.aligned.m16n8k16.row.col.f32.bf16.bf16.f32 " \
        "{%0,%1,%2,%3}, {%4,%5,%6,%7}, {%8,%9}, {%0,%1,%2,%3};" \
        : "+f"((c)[0]), "+f"((c)[1]), "+f"((c)[2]), "+f"((c)[3]) \
        : "r"((a)[0]), "r"((a)[1]), "r"((a)[2]), "r"((a)[3]), "r"(b0v), "r"(b1v))

__device__ __forceinline__ void bulk_cp(unsigned dst, const void* src,
                                        unsigned bytes, unsigned mbar) {
    asm volatile(
        "cp.async.bulk.shared::cta.global.mbarrier::complete_tx::bytes [%0], [%1], %2, [%3];"
        :: "r"(dst), "l"(src), "r"(bytes), "r"(mbar) : "memory");
}
__device__ __forceinline__ void mbar_expect(unsigned mbar, unsigned bytes) {
    asm volatile("mbarrier.arrive.expect_tx.shared.b64 _, [%0], %1;"
                 :: "r"(mbar), "r"(bytes) : "memory");
}
__device__ __forceinline__ unsigned sw128(unsigned byo) {
    return byo ^ ((byo >> 3) & 0x70);
}
__device__ __forceinline__ unsigned bf2u(__nv_bfloat162 h) {
    return *(unsigned*)&h;
}

// ---------------- K1: rep-only bag pooling (exact R8) -----------------------
__global__ void __launch_bounds__(256) k_bag(
    const float* __restrict__ rep,
    const float* __restrict__ rel_table, const int* __restrict__ labels)
{
    __shared__ float s_scores[BAG_];
    __shared__ float s_alpha[BAG_];
    __shared__ float s_red[8];

    int b = blockIdx.x;
    int tid = threadIdx.x, wid = tid >> 5, lane = tid & 31;
    const float* repb = rep + (size_t)b * BAG_ * H_;
    const float4* rel4 = (const float4*)(rel_table + (size_t)labels[b] * H_);

    #pragma unroll
    for (int q = 0; q < 2; ++q)
        g_negp[wid + q * 8][b * BAG_ + lane] = 0.0f;
    if (b == 0 && tid == 0) g_lsum = 0.0f;

    for (int j = wid; j < BAG_; j += 8) {
        const float4* r4 = (const float4*)(repb + (size_t)j * H_);
        int n = b * BAG_ + j;
        char* dstb = (char*)g_rep_bf + (size_t)(n >> 3) * 1024;
        unsigned inoff = sw128((unsigned)(n & 7) * 128u + (unsigned)(lane & 15) * 8u);
        float ds = 0.f, dr = 0.f;
        #pragma unroll
        for (int i = 0; i < 8; ++i) {
            int t = lane + 32 * i;
            float4 rv = r4[t];
            float4 rl = rel4[t];
            uint2 pk;
            pk.x = bf2u(__floats2bfloat162_rn(rv.x, rv.y));
            pk.y = bf2u(__floats2bfloat162_rn(rv.z, rv.w));
            unsigned kc = (unsigned)(lane >> 4) + 2u * i;
            *(uint2*)(dstb + (size_t)kc * (N_ * 128) + inoff) = pk;
            ds = fmaf(rl.x, rv.x, fmaf(rl.y, rv.y, fmaf(rl.z, rv.z, fmaf(rl.w, rv.w, ds))));
            dr = fmaf(rv.x, rv.x, fmaf(rv.y, rv.y, fmaf(rv.z, rv.z, fmaf(rv.w, rv.w, dr))));
        }
        ds = warp_sum(ds); dr = warp_sum(dr);
        if (lane == 0) {
            s_scores[j] = ds * (1.0f / 32.0f);          // / sqrt(H)
            g_rnr[n] = 1.0f / sqrtf(dr);
        }
    }
    __syncthreads();

    if (tid < 32) {
        float v = s_scores[tid];
        float m = warp_max(v);
        float e = expf(v - m);
        float s = warp_sum(e);
        s = __shfl_sync(0xffffffffu, s, 0);
        s_alpha[tid] = e / s;
    }
    __syncthreads();

    const float4* rp4 = (const float4*)repb;
    float4 acc = make_float4(0.f, 0.f, 0.f, 0.f);
    #pragma unroll 8
    for (int j = 0; j < BAG_; ++j) {
        float4 v = rp4[(size_t)j * 256 + tid];
        float a = s_alpha[j];
        acc.x = fmaf(a, v.x, acc.x); acc.y = fmaf(a, v.y, acc.y);
        acc.z = fmaf(a, v.z, acc.z); acc.w = fmaf(a, v.w, acc.w);
    }
    ((float4*)g_bag)[(size_t)b * 256 + tid] = acc;
    {
        uint2 pk;
        pk.x = bf2u(__floats2bfloat162_rn(acc.x, acc.y));
        pk.y = bf2u(__floats2bfloat162_rn(acc.z, acc.w));
        unsigned kc = (unsigned)tid >> 4;
        unsigned sw = sw128((unsigned)(b & 7) * 128u + (unsigned)(tid & 15) * 8u);
        *(uint2*)((char*)g_bag_bf + (size_t)kc * (B_ * 128) + (size_t)(b >> 3) * 1024 + sw) = pk;
    }
    float nb_part = fmaf(acc.x, acc.x, fmaf(acc.y, acc.y, fmaf(acc.z, acc.z, acc.w * acc.w)));
    nb_part = warp_sum(nb_part);
    if (lane == 0) s_red[wid] = nb_part;
    __syncthreads();
    if (tid == 0) {
        float s = 0.f;
        #pragma unroll
        for (int w = 0; w < 8; ++w) s += s_red[w];
        g_rnb[b] = 1.0f / sqrtf(s);
    }
}

// ---------------- K1b: pos term (off critical path, overlaps k_pair) -------
__global__ void __launch_bounds__(256) k_pos(
    const float* __restrict__ rep, const float* __restrict__ aug,
    const float* __restrict__ tptr)
{
    int b = blockIdx.x;
    int tid = threadIdx.x, wid = tid >> 5, lane = tid & 31;
    float invT = 1.0f / tptr[0];

    for (int j = wid; j < BAG_; j += 8) {
        int n = b * BAG_ + j;
        const float4* r4 = (const float4*)(rep + (size_t)n * H_);
        const float4* a4 = (const float4*)(aug + (size_t)n * H_);
        float da = 0.f, dra = 0.f;
        #pragma unroll
        for (int i = 0; i < 8; ++i) {
            int t = lane + 32 * i;
            float4 rv = r4[t], av = a4[t];
            da  = fmaf(av.x, av.x, fmaf(av.y, av.y, fmaf(av.z, av.z, fmaf(av.w, av.w, da))));
            dra = fmaf(rv.x, av.x, fmaf(rv.y, av.y, fmaf(rv.z, av.z, fmaf(rv.w, av.w, dra))));
        }
        da = warp_sum(da); dra = warp_sum(dra);
        if (lane == 0) {
            float na = sqrtf(da);
            float nr = 1.0f / g_rnr[n];
            float psim = dra / fmaxf(nr * na, EPS_);
            g_pos[n] = expf(psim * invT);
        }
    }
}

// ---------------- K2: classifier, 64 blocks x 8 bag rows -------------------
__global__ void __launch_bounds__(256) k_clsout(
    const float* __restrict__ cls_w, const float* __restrict__ cls_b,
    float* __restrict__ out)
{
    __shared__ float4 sbag[8][256];
    int tid = threadIdx.x, wid = tid >> 5, lane = tid & 31;
    int b0 = blockIdx.x * 8;
    for (int idx = tid; idx < 2048; idx += 256)
        sbag[idx >> 8][idx & 255] =
            ((const float4*)g_bag)[(size_t)(b0 + (idx >> 8)) * 256 + (idx & 255)];
    __syncthreads();

    for (int c0 = wid * 2; c0 < C_; c0 += 16) {
        int c1 = c0 + 1;
        bool has1 = c1 < C_;
        const float4* w0 = (const float4*)(cls_w + (size_t)c0 * H_);
        const float4* w1 = (const float4*)(cls_w + (size_t)(has1 ? c1 : c0) * H_);
        float acc0[8] = {}, acc1[8] = {};
        for (int i = lane; i < 256; i += 32) {
            float4 wa = w0[i], wb = w1[i];
            #pragma unroll
            for (int r = 0; r < 8; ++r) {
                float4 v = sbag[r][i];
                acc0[r] = fmaf(wa.x, v.x, fmaf(wa.y, v.y, fmaf(wa.z, v.z, fmaf(wa.w, v.w, acc0[r]))));
                acc1[r] = fmaf(wb.x, v.x, fmaf(wb.y, v.y, fmaf(wb.z, v.z, fmaf(wb.w, v.w, acc1[r]))));
            }
        }
        #pragma unroll
        for (int r = 0; r < 8; ++r) {
            float s0 = warp_sum(acc0[r]);
            float s1 = warp_sum(acc1[r]);
            if (lane == 0) {
                out[(b0 + r) * C_ + c0] = s0 + cls_b[c0];
                if (has1) out[(b0 + r) * C_ + c1] = s1 + cls_b[c1];
            }
        }
    }
}

// ---------------- K3: bf16 HMMA pair GEMM (exact R8) ------------------------
#define STAGES 3
#define STAGE_BYTES 32768
#define NKC 16
#define PAIR_SMEM (STAGES * STAGE_BYTES)   // 98304

__global__ void __launch_bounds__(256, 2) k_pair_hmma(const float* __restrict__ tptr)
{
    extern __shared__ __align__(16) char smem[];
    __shared__ __align__(8) unsigned long long mbars[2 * STAGES];
    unsigned smem_u = (unsigned)__cvta_generic_to_shared(smem);
    unsigned mbar_u = (unsigned)__cvta_generic_to_shared(mbars);
    int tid = threadIdx.x, wid = tid >> 5, lane = tid & 31;
    int wm = wid >> 2, wn = wid & 3;
    int m0 = blockIdx.y * 128, n0 = blockIdx.x * 128;

    if (tid == 0) {
        #pragma unroll
        for (int s = 0; s < STAGES; ++s) {
            MBAR_INIT(mbar_u + 8 * s, 1);
            MBAR_INIT(mbar_u + 8 * (STAGES + s), 8);
        }
    }
    __syncthreads();

    const char* Asrc = (const char*)g_bag_bf;
    const char* Bsrc = (const char*)g_rep_bf;
    if (tid == 0) {
        #pragma unroll
        for (int s = 0; s < STAGES; ++s) {
            unsigned mb = mbar_u + 8 * s;
            mbar_expect(mb, 2 * 16384u);
            unsigned d = smem_u + s * STAGE_BYTES;
            bulk_cp(d,          Asrc + ((size_t)s * B_ + m0) * 128, 16384u, mb);
            bulk_cp(d + 16384u, Bsrc + ((size_t)s * N_ + n0) * 128, 16384u, mb);
        }
    }

    unsigned xr   = (unsigned)(lane & 7) * 16u;
    unsigned hk16 = (unsigned)(lane >> 4) * 16u;
    unsigned kb16 = (unsigned)((lane >> 3) & 1) * 16u;
    unsigned aoffb = (unsigned)((wm * 64 + (lane & 15)) * 128);
    unsigned boffb = (unsigned)((wn * 32 + ((lane >> 4) & 1) * 8 + (lane & 7)) * 128) + 16384u;

    float acc[4][4][4] = {};

    #pragma unroll 1
    for (int kc = 0; kc < NKC; ++kc) {
        int st = kc % 3;
        unsigned u = (unsigned)(kc / 3);
        MBAR_WAIT(mbar_u + 8 * st, u & 1);
        unsigned base = smem_u + st * STAGE_BYTES;
        #pragma unroll
        for (int ks = 0; ks < 4; ++ks) {
            unsigned afr[4][4], bfr[2][4];
            unsigned ksa = ((unsigned)(ks * 32) + hk16) ^ xr;
            unsigned ksb = ((unsigned)(ks * 32) + kb16) ^ xr;
            #pragma unroll
            for (int mt = 0; mt < 4; ++mt)
                LDSM4(afr[mt], base + aoffb + mt * 2048u + ksa);
            #pragma unroll
            for (int np = 0; np < 2; ++np)
                LDSM4(bfr[np], base + boffb + np * 2048u + ksb);
            #pragma unroll
            for (int mt = 0; mt < 4; ++mt)
                #pragma unroll
                for (int nt = 0; nt < 4; ++nt)
                    MMA_BF16(acc[mt][nt], afr[mt],
                             bfr[nt >> 1][(nt & 1) * 2], bfr[nt >> 1][(nt & 1) * 2 + 1]);
        }
        if (lane == 0) MBAR_ARRIVE(mbar_u + 8 * (STAGES + st));
        if (kc + STAGES < NKC && wid == (kc & 7) && lane == 0) {
            MBAR_WAIT(mbar_u + 8 * (STAGES + st), u & 1);
            unsigned mb = mbar_u + 8 * st;
            mbar_expect(mb, 2 * 16384u);
            unsigned d = smem_u + st * STAGE_BYTES;
            bulk_cp(d,          Asrc + ((size_t)(kc + STAGES) * B_ + m0) * 128, 16384u, mb);
            bulk_cp(d + 16384u, Bsrc + ((size_t)(kc + STAGES) * N_ + n0) * 128, 16384u, mb);
        }
    }
    __syncthreads();

    // ---- epilogue: FMA-pipe exp, single-pass smem reduce, slotted atomics ----
    float* sbuf  = (float*)smem;                    // [4][128][33]
    float* s_rnr = (float*)(smem + 67584);
    float* s_rnb = (float*)(smem + 67584 + 512);
    if (tid < 128) { s_rnr[tid] = g_rnr[n0 + tid]; s_rnb[tid] = g_rnb[m0 + tid]; }
    __syncthreads();
    float invT = 1.0f / tptr[0];
    int bglob = (n0 >> 5) + wn;
    int r0base = wm * 64 + (lane >> 2);
    float* negslot = g_negp[blockIdx.x & (NSLOT - 1)];
    float* wbuf = sbuf + wn * (128 * 33);

    #pragma unroll
    for (int mt = 0; mt < 4; ++mt) {
        int r0 = r0base + mt * 16, r1 = r0 + 8;
        float f0 = s_rnb[r0] * invT, f1 = s_rnb[r1] * invT;
        bool sk0 = (m0 + r0) == bglob, sk1 = (m0 + r1) == bglob;
        #pragma unroll
        for (int nt = 0; nt < 4; ++nt) {
            int jj = nt * 8 + (lane & 3) * 2;
            float rn0 = s_rnr[wn * 32 + jj], rn1 = s_rnr[wn * 32 + jj + 1];
            float e00 = sk0 ? 0.f : fexp(acc[mt][nt][0] * f0 * rn0);
            float e01 = sk0 ? 0.f : fexp(acc[mt][nt][1] * f0 * rn1);
            float e10 = sk1 ? 0.f : fexp(acc[mt][nt][2] * f1 * rn0);
            float e11 = sk1 ? 0.f : fexp(acc[mt][nt][3] * f1 * rn1);
            wbuf[r0 * 33 + jj]     = e00;
            wbuf[r0 * 33 + jj + 1] = e01;
            wbuf[r1 * 33 + jj]     = e10;
            wbuf[r1 * 33 + jj + 1] = e11;
        }
    }
    __syncthreads();
    for (int e = tid; e < 4096; e += 256) {
        int lc = e >> 5, jj = e & 31;
        float v = sbuf[lc * 33 + jj]
                + sbuf[1 * (128 * 33) + lc * 33 + jj]
                + sbuf[2 * (128 * 33) + lc * 33 + jj]
                + sbuf[3 * (128 * 33) + lc * 33 + jj];
        atomicAdd(&negslot[(m0 + lc) * BAG_ + jj], v);
    }
}

// ---------------- K4: loss (128 blocks x 128 threads) ----------------------
__global__ void __launch_bounds__(128) k_loss(const float* __restrict__ pos,
                                              float* __restrict__ out, int loss_idx) {
    int i = blockIdx.x * 128 + threadIdx.x;
    float t = 0.f;
    #pragma unroll
    for (int s = 0; s < NSLOT; ++s) t += g_negp[s][i];
    float v = __logf(1.0f + __fdividef(t, pos[i]));
    v = warp_sum(v);
    __shared__ float sr[4];
    if ((threadIdx.x & 31) == 0) sr[threadIdx.x >> 5] = v;
    __syncthreads();
    if (threadIdx.x == 0) {
        float s = sr[0] + sr[1] + sr[2] + sr[3];
        atomicAdd(&g_lsum, s);
        __threadfence();
        if (atomicAdd(&g_cnt, 1) == (N_ / 128) - 1) {
            out[loss_idx] = g_lsum * (1.0f / (float)N_);
            g_cnt = 0;
        }
    }
}

// ---------------- launch (exact R8 graph) -----------------------------------
extern "C" void kernel_launch(void* const* d_in, const int* in_sizes, int n_in,
                              void* d_out, int out_size) {
    const float* rep    = (const float*)d_in[0];
    const float* aug    = (const float*)d_in[1];
    const float* rel    = (const float*)d_in[2];
    const float* cls_w  = (const float*)d_in[3];
    const float* cls_b  = (const float*)d_in[4];
    const int*   labels = (const int*)d_in[5];
    const float* temp   = (const float*)d_in[6];
    float* out = (float*)d_out;

    static cudaStream_t s2 = nullptr;
    static cudaEvent_t evA = nullptr, evB = nullptr;
    if (!s2) {
        cudaFuncSetAttribute(k_pair_hmma, cudaFuncAttributeMaxDynamicSharedMemorySize, PAIR_SMEM);
        cudaStreamCreateWithFlags(&s2, cudaStreamNonBlocking);
        cudaEventCreateWithFlags(&evA, cudaEventDisableTiming);
        cudaEventCreateWithFlags(&evB, cudaEventDisableTiming);
    }

    // critical path: k_bag -> k_pair -> k_loss
    k_bag<<<B_, 256>>>(rep, rel, labels);

    // fork: classifier + pos run on s2, overlapping the pair GEMM
    cudaEventRecord(evA, 0);
    cudaStreamWaitEvent(s2, evA, 0);
    k_clsout<<<B_ / 8, 256, 0, s2>>>(cls_w, cls_b, out);
    k_pos<<<B_, 256, 0, s2>>>(rep, aug, temp);
    cudaEventRecord(evB, s2);

    dim3 g3(N_ / 128, B_ / 128);   // (128, 4)
    k_pair_hmma<<<g3, 256, PAIR_SMEM>>>(temp);

    // join: k_loss needs g_pos (s2) and g_negp (main)
    cudaStreamWaitEvent(0, evB, 0);
    float* g_pos_ptr = nullptr;
    cudaGetSymbolAddress((void**)&g_pos_ptr, g_pos);
    k_loss<<<N_ / 128, 128>>>(g_pos_ptr, out, out_size - 1);
}